// round 6
// baseline (speedup 1.0000x reference)
#include <cuda_runtime.h>
#include <cstdint>

typedef unsigned long long ULL;
typedef unsigned char u8;

// ---------------- problem dims ----------------
#define T_  4
#define B_  8
#define S_  1024
#define D_  768
#define HF_ 3072
#define SD_   (S_*D_)
#define SH_   (S_*HF_)
#define BSD_  (B_*SD_)
#define BSH_  (B_*SH_)
#define TBSD_ (T_*BSD_)
#define TBSH_ (T_*BSH_)
#define TBD_  (T_*B_*D_)
#define BD_   (B_*D_)
#define MROWS_ (T_*B_*S_)

#define KC_  256   // Eigen gebp k-panel (confirmed R4)

// bn-stat stages
#define ST_Q   0
#define ST_V   1
#define ST_K   2
#define ST_ATT 3
#define ST_O1  4
#define ST_O2  5

// ---------------- device scratch ----------------
__device__ u8    g_sp  [TBSD_];
__device__ float g_q   [TBSD_];
__device__ float g_k   [TBSD_];
__device__ float g_v   [TBSD_];
__device__ u8    g_qs  [TBSD_];
__device__ u8    g_ks  [TBSD_];
__device__ u8    g_vs  [TBSD_];
__device__ u8    g_qkvm[TBSD_];
__device__ float g_att [TBSD_];
__device__ float g_h   [TBSD_];
__device__ u8    g_sp2 [TBSD_];
__device__ float g_o1  [TBSH_];
__device__ u8    g_s1  [TBSH_];
__device__ float g_o2  [TBSD_];
__device__ int   g_qkp [4*TBD_];
__device__ u8    g_qks [TBD_];
__device__ float g_part[8*512];
__device__ float g_mean [6*8];
__device__ float g_denom[6*8];

// pointer tables (capture-safe: host never queries symbols)
__device__ u8*    g_ptrB[4];
__device__ float* g_ptrF[6];
__global__ void k_init_ptrs() {
    if (threadIdx.x == 0 && blockIdx.x == 0) {
        g_ptrB[0] = g_sp;  g_ptrB[1] = g_qkvm; g_ptrB[2] = g_sp2; g_ptrB[3] = g_s1;
        g_ptrF[0] = g_q;   g_ptrF[1] = g_k;    g_ptrF[2] = g_v;
        g_ptrF[3] = g_att; g_ptrF[4] = g_o1;   g_ptrF[5] = g_o2;
    }
}

// ---------------- f32x2 helpers (bitwise 2x IEEE fp32 ops) ----------------
__device__ __forceinline__ ULL pack2(float v) {
    ULL r; asm("mov.b64 %0, {%1, %1};" : "=l"(r) : "f"(v)); return r;
}
__device__ __forceinline__ void fma2(ULL& d, ULL a, ULL b) {
    asm("fma.rn.f32x2 %0, %1, %2, %0;" : "+l"(d) : "l"(a), "l"(b));
}
__device__ __forceinline__ ULL add2(ULL a, ULL b) {
    ULL r; asm("add.rn.f32x2 %0, %1, %2;" : "=l"(r) : "l"(a), "l"(b)); return r;
}
__device__ __forceinline__ float2 unpack2(ULL v) {
    float2 r; asm("mov.b64 {%0, %1}, %2;" : "=f"(r.x), "=f"(r.y) : "l"(v)); return r;
}

// ---------------- SGEMM v3 ----------------
// C[M,N] = A[M,K] @ B[K,N] (+bias), A = binary spikes (uint8).
// 128x128 tile, BK=8, 256 threads, 8x8 microtile.
// Chain-preserving Eigen emulation (bitwise = R4): per output, serial
// ascending-k FFMA chain in 'part'; every 256 k's FADD-combined into 'acc'
// (registers) in ascending panel order; bias added once at the end.
// A pre-duplicated into f32x2 ULLs at smem-store time (no packs in inner loop).
// Static smem only (24 KB), ping-pong, one sync per tile.
__global__ __launch_bounds__(256, 2)
void sgemm3(int aSel, const float* __restrict__ Bm, const float* __restrict__ bias,
            int cSel, int N, int K)
{
    __shared__ __align__(16) ULL   AsP[2][8][128];  // 16 KB
    __shared__ __align__(16) float Bs [2][8][128];  //  8 KB

    const u8* __restrict__ A = g_ptrB[aSel];
    float* __restrict__ C = g_ptrF[cSel];

    const int tid = threadIdx.x;
    const int bn = blockIdx.x, bm = blockIdx.y;
    const int tx = tid & 15, ty = tid >> 4;
    const int arow = tid >> 1, acol = (tid & 1) * 4;
    const int brow = tid >> 5, bcol = (tid & 31) * 4;

    const u8*    Ag = A  + (size_t)(bm * 128 + arow) * K + acol;
    const float* Bg = Bm + (size_t)brow * N + bn * 128 + bcol;

    ULL acc[8][4], part[8][4];
#pragma unroll
    for (int i = 0; i < 8; i++)
#pragma unroll
        for (int j = 0; j < 4; j++) { acc[i][j] = 0ULL; part[i][j] = 0ULL; }

    // prefetch + store tile 0
    uchar4 av = *(const uchar4*)(Ag);
    float4 bv = *(const float4*)(Bg);
    AsP[0][acol + 0][arow] = pack2((float)av.x);
    AsP[0][acol + 1][arow] = pack2((float)av.y);
    AsP[0][acol + 2][arow] = pack2((float)av.z);
    AsP[0][acol + 3][arow] = pack2((float)av.w);
    *(float4*)&Bs[0][brow][bcol] = bv;
    __syncthreads();

    int buf = 0;
    for (int k0 = 0; k0 < K; k0 += 8) {
        const bool more = (k0 + 8) < K;
        if (more) {
            av = *(const uchar4*)(Ag + k0 + 8);
            bv = *(const float4*)(Bg + (size_t)(k0 + 8) * N);
        }

#pragma unroll
        for (int kk = 0; kk < 8; kk++) {
            ULL a_[8], b_[4];
            const ULL* ap = &AsP[buf][kk][ty * 8];
#pragma unroll
            for (int i = 0; i < 8; i++) a_[i] = ap[i];
            const ULL* bp = (const ULL*)&Bs[buf][kk][tx * 8];
#pragma unroll
            for (int j = 0; j < 4; j++) b_[j] = bp[j];
#pragma unroll
            for (int i = 0; i < 8; i++)
#pragma unroll
                for (int j = 0; j < 4; j++) fma2(part[i][j], a_[i], b_[j]);
        }

        if (more) {
            int nb = buf ^ 1;
            AsP[nb][acol + 0][arow] = pack2((float)av.x);
            AsP[nb][acol + 1][arow] = pack2((float)av.y);
            AsP[nb][acol + 2][arow] = pack2((float)av.z);
            AsP[nb][acol + 3][arow] = pack2((float)av.w);
            *(float4*)&Bs[nb][brow][bcol] = bv;
            __syncthreads();
        }

        // Eigen panel boundary: FADD-flush serial chain into outer accumulator
        if (((k0 + 8) & (KC_ - 1)) == 0) {
#pragma unroll
            for (int i = 0; i < 8; i++)
#pragma unroll
                for (int j = 0; j < 4; j++) {
                    acc[i][j] = add2(acc[i][j], part[i][j]);
                    part[i][j] = 0ULL;
                }
        }
        buf ^= 1;
    }

    float bb[8];
#pragma unroll
    for (int j = 0; j < 8; j++)
        bb[j] = bias ? bias[bn * 128 + tx * 8 + j] : 0.0f;

#pragma unroll
    for (int i = 0; i < 8; i++) {
        float* Cp = C + (size_t)(bm * 128 + ty * 8 + i) * N + bn * 128 + tx * 8;
        float2 p0 = unpack2(acc[i][0]), p1 = unpack2(acc[i][1]);
        float2 p2 = unpack2(acc[i][2]), p3 = unpack2(acc[i][3]);
        *(float4*)Cp       = make_float4(p0.x + bb[0], p0.y + bb[1], p1.x + bb[2], p1.y + bb[3]);
        *(float4*)(Cp + 4) = make_float4(p2.x + bb[4], p2.y + bb[5], p3.x + bb[6], p3.y + bb[7]);
    }
}

// ---------------- IF on input x -> sp bytes ----------------
__global__ void k_ifx(const float* __restrict__ x) {
    int j = blockIdx.x * blockDim.x + threadIdx.x;
    if (j >= BSD_) return;
    float vm = 0.0f;
#pragma unroll
    for (int t = 0; t < T_; t++) {
        int idx = t * BSD_ + j;
        vm += x[idx];
        float s = (vm >= 1.0f) ? 1.0f : 0.0f;
        g_sp[idx] = (u8)s;
        vm *= (1.0f - s);
    }
}

// ---------------- BN pass A: per-batch sum -> mean ----------------
__global__ void k_redA(int sel, int SDv) {
    const float* __restrict__ X = g_ptrF[sel];
    int b = blockIdx.y;
    int E = T_ * SDv;
    float s = 0.0f;
    for (int i = blockIdx.x * 256 + threadIdx.x; i < E; i += 512 * 256) {
        int t = i / SDv;
        int r = i - t * SDv;
        s += X[(size_t)(t * B_ + b) * SDv + r];
    }
    __shared__ float sh[256];
    int tid = threadIdx.x;
    sh[tid] = s; __syncthreads();
    for (int o = 128; o > 0; o >>= 1) { if (tid < o) sh[tid] += sh[tid + o]; __syncthreads(); }
    if (tid == 0) g_part[b * 512 + blockIdx.x] = sh[0];
}

__global__ void k_finA(int SDv, int stage) {
    int b = blockIdx.x, tid = threadIdx.x;
    double s = (double)g_part[b * 512 + tid] + (double)g_part[b * 512 + tid + 256];
    __shared__ double sh[256];
    sh[tid] = s; __syncthreads();
    for (int o = 128; o > 0; o >>= 1) { if (tid < o) sh[tid] += sh[tid + o]; __syncthreads(); }
    if (tid == 0) {
        float E = (float)(T_ * SDv);
        g_mean[stage * 8 + b] = __fdiv_rn((float)sh[0], E);
    }
}

// ---------------- BN pass B: per-batch sum of (x-m)^2 -> denom ----------------
__global__ void k_redB(int sel, int SDv, int stage) {
    const float* __restrict__ X = g_ptrF[sel];
    int b = blockIdx.y;
    float m = g_mean[stage * 8 + b];
    int E = T_ * SDv;
    float s = 0.0f;
    for (int i = blockIdx.x * 256 + threadIdx.x; i < E; i += 512 * 256) {
        int t = i / SDv;
        int r = i - t * SDv;
        float v = X[(size_t)(t * B_ + b) * SDv + r] - m;
        s += v * v;
    }
    __shared__ float sh[256];
    int tid = threadIdx.x;
    sh[tid] = s; __syncthreads();
    for (int o = 128; o > 0; o >>= 1) { if (tid < o) sh[tid] += sh[tid + o]; __syncthreads(); }
    if (tid == 0) g_part[b * 512 + blockIdx.x] = sh[0];
}

__global__ void k_finB(int SDv, int stage) {
    int b = blockIdx.x, tid = threadIdx.x;
    double s = (double)g_part[b * 512 + tid] + (double)g_part[b * 512 + tid + 256];
    __shared__ double sh[256];
    sh[tid] = s; __syncthreads();
    for (int o = 128; o > 0; o >>= 1) { if (tid < o) sh[tid] += sh[tid + o]; __syncthreads(); }
    if (tid == 0) {
        float E = (float)(T_ * SDv);
        float var_f = __fdiv_rn((float)sh[0], E);
        g_denom[stage * 8 + b] = __fsqrt_rn(var_f + 1e-5f);
    }
}

// ---------------- fused BN + IF over Q,V,K with CARRIED membrane ----------------
__global__ void k_ifqvk() {
    int j = blockIdx.x * 256 + threadIdx.x;
    if (j >= BSD_) return;
    int b = j / SD_;
    float mq = g_mean[ST_Q * 8 + b], dq = g_denom[ST_Q * 8 + b];
    float mv = g_mean[ST_V * 8 + b], dv = g_denom[ST_V * 8 + b];
    float mk = g_mean[ST_K * 8 + b], dk = g_denom[ST_K * 8 + b];
    float vm = 0.0f;
#pragma unroll
    for (int t = 0; t < T_; t++) {
        int idx = t * BSD_ + j;
        vm += __fdiv_rn(g_q[idx] - mq, dq);
        float s = (vm >= 1.0f) ? 1.0f : 0.0f;
        g_qs[idx] = (u8)s;
        vm *= (1.0f - s);
    }
#pragma unroll
    for (int t = 0; t < T_; t++) {
        int idx = t * BSD_ + j;
        vm += __fdiv_rn(g_v[idx] - mv, dv);
        float s = (vm >= 1.0f) ? 1.0f : 0.0f;
        g_vs[idx] = (u8)s;
        vm *= (1.0f - s);
    }
#pragma unroll
    for (int t = 0; t < T_; t++) {
        int idx = t * BSD_ + j;
        vm += __fdiv_rn(g_k[idx] - mk, dk);
        float s = (vm >= 1.0f) ? 1.0f : 0.0f;
        g_ks[idx] = (u8)s;
        vm *= (1.0f - s);
    }
}

// ---------------- QK: integer seq-reduction (exact) ----------------
__global__ void k_qk() {
    int d = blockIdx.x * 256 + threadIdx.x;
    int tb = blockIdx.y;
    int sp = blockIdx.z;
    int acc = 0;
    int s0 = sp * 256;
    for (int s = s0; s < s0 + 256; s++) {
        size_t idx = ((size_t)tb * S_ + s) * D_ + d;
        acc += (int)(g_qs[idx] & g_ks[idx]);
    }
    g_qkp[sp * TBD_ + tb * D_ + d] = acc;
}

// QKs = IF(QK) over t (integers exact in fp32)
__global__ void k_qks() {
    int i = blockIdx.x * 256 + threadIdx.x;
    if (i >= BD_) return;
    int b = i / D_, d = i - b * D_;
    float vm = 0.0f;
#pragma unroll
    for (int t = 0; t < T_; t++) {
        int idx = (t * B_ + b) * D_ + d;
        int qk = g_qkp[idx] + g_qkp[TBD_ + idx] + g_qkp[2 * TBD_ + idx] +
                 g_qkp[3 * TBD_ + idx];
        vm += (float)qk;
        float s = (vm >= 1.0f) ? 1.0f : 0.0f;
        g_qks[idx] = (u8)s;
        vm *= (1.0f - s);
    }
}

// QKV spikes = Vs & QKs
__global__ void k_qkvm() {
    int idx = blockIdx.x * 256 + threadIdx.x;
    if (idx >= TBSD_) return;
    int d = idx % D_;
    int tb = idx / SD_;
    g_qkvm[idx] = g_vs[idx] & g_qks[tb * D_ + d];
}

// h = sp + bn(att); sp2 = IF(h)
__global__ void k_hsp2() {
    int j = blockIdx.x * 256 + threadIdx.x;
    if (j >= BSD_) return;
    int b = j / SD_;
    float m = g_mean[ST_ATT * 8 + b], dn = g_denom[ST_ATT * 8 + b];
    float vm = 0.0f;
#pragma unroll
    for (int t = 0; t < T_; t++) {
        int idx = t * BSD_ + j;
        float hval = (float)g_sp[idx] + __fdiv_rn(g_att[idx] - m, dn);
        g_h[idx] = hval;
        vm += hval;
        float s = (vm >= 1.0f) ? 1.0f : 0.0f;
        g_sp2[idx] = (u8)s;
        vm *= (1.0f - s);
    }
}

// s1 = IF(bn(o1))
__global__ void k_s1() {
    int j = blockIdx.x * 256 + threadIdx.x;
    if (j >= BSH_) return;
    int b = j / SH_;
    float m = g_mean[ST_O1 * 8 + b], dn = g_denom[ST_O1 * 8 + b];
    float vm = 0.0f;
#pragma unroll
    for (int t = 0; t < T_; t++) {
        int idx = t * BSH_ + j;
        vm += __fdiv_rn(g_o1[idx] - m, dn);
        float s = (vm >= 1.0f) ? 1.0f : 0.0f;
        g_s1[idx] = (u8)s;
        vm *= (1.0f - s);
    }
}

// out = h + bn(o2)
__global__ void k_out(float* __restrict__ out) {
    int idx = blockIdx.x * 256 + threadIdx.x;
    if (idx >= TBSD_) return;
    int b = (idx / SD_) % B_;
    float m = g_mean[ST_O2 * 8 + b], dn = g_denom[ST_O2 * 8 + b];
    out[idx] = g_h[idx] + __fdiv_rn(g_o2[idx] - m, dn);
}

// ---------------- launch (kernel launches ONLY — capture-safe) ----------------
extern "C" void kernel_launch(void* const* d_in, const int* in_sizes, int n_in,
                              void* d_out, int out_size) {
    (void)in_sizes; (void)n_in; (void)out_size;
    const float* x  = (const float*)d_in[0];
    const float* wq = (const float*)d_in[1];
    const float* wk = (const float*)d_in[2];
    const float* wv = (const float*)d_in[3];
    const float* wo = (const float*)d_in[4];
    const float* w1 = (const float*)d_in[5];
    const float* b1 = (const float*)d_in[6];
    const float* w2 = (const float*)d_in[7];
    const float* b2 = (const float*)d_in[8];
    float* out = (float*)d_out;

    const int EW = 256;
    k_init_ptrs<<<1, 32>>>();

    // 1) sp = IF(x)
    k_ifx<<<BSD_ / EW, EW>>>(x);

    // 2) Q,K,V GEMMs (A = sp bytes)
    sgemm3<<<dim3(6, 256), 256>>>(0, wq, nullptr, 0, D_, D_);
    sgemm3<<<dim3(6, 256), 256>>>(0, wk, nullptr, 1, D_, D_);
    sgemm3<<<dim3(6, 256), 256>>>(0, wv, nullptr, 2, D_, D_);

    // 3) BN stats (two-pass) for Q, V, K
    k_redA<<<dim3(512, 8), 256>>>(0, SD_); k_finA<<<8, 256>>>(SD_, ST_Q);
    k_redB<<<dim3(512, 8), 256>>>(0, SD_, ST_Q); k_finB<<<8, 256>>>(SD_, ST_Q);
    k_redA<<<dim3(512, 8), 256>>>(2, SD_); k_finA<<<8, 256>>>(SD_, ST_V);
    k_redB<<<dim3(512, 8), 256>>>(2, SD_, ST_V); k_finB<<<8, 256>>>(SD_, ST_V);
    k_redA<<<dim3(512, 8), 256>>>(1, SD_); k_finA<<<8, 256>>>(SD_, ST_K);
    k_redB<<<dim3(512, 8), 256>>>(1, SD_, ST_K); k_finB<<<8, 256>>>(SD_, ST_K);

    // 4) fused BN+IF, membrane carried Q -> V -> K
    k_ifqvk<<<BSD_ / EW, EW>>>();

    // 5) QK (integer) + IF + QKV spikes
    k_qk<<<dim3(D_ / 256, T_ * B_, 4), 256>>>();
    k_qks<<<BD_ / EW, EW>>>();
    k_qkvm<<<TBSD_ / EW, EW>>>();

    // 6) att = QKV @ wo + BN stats
    sgemm3<<<dim3(6, 256), 256>>>(1, wo, nullptr, 3, D_, D_);
    k_redA<<<dim3(512, 8), 256>>>(3, SD_); k_finA<<<8, 256>>>(SD_, ST_ATT);
    k_redB<<<dim3(512, 8), 256>>>(3, SD_, ST_ATT); k_finB<<<8, 256>>>(SD_, ST_ATT);

    // 7) h = sp + bn(att); sp2 = IF(h)
    k_hsp2<<<BSD_ / EW, EW>>>();

    // 8) o1 = sp2 @ w1 + b1; BN; s1 = IF(bn(o1))
    sgemm3<<<dim3(24, 256), 256>>>(2, w1, b1, 4, HF_, D_);
    k_redA<<<dim3(512, 8), 256>>>(4, SH_); k_finA<<<8, 256>>>(SH_, ST_O1);
    k_redB<<<dim3(512, 8), 256>>>(4, SH_, ST_O1); k_finB<<<8, 256>>>(SH_, ST_O1);
    k_s1<<<BSH_ / EW, EW>>>();

    // 9) o2 = s1 @ w2 + b2; BN
    sgemm3<<<dim3(6, 256), 256>>>(3, w2, b2, 5, D_, HF_);
    k_redA<<<dim3(512, 8), 256>>>(5, SD_); k_finA<<<8, 256>>>(SD_, ST_O2);
    k_redB<<<dim3(512, 8), 256>>>(5, SD_, ST_O2); k_finB<<<8, 256>>>(SD_, ST_O2);

    // 10) out = h + bn(o2)
    k_out<<<TBSD_ / EW, EW>>>(out);
}

// round 7
// speedup vs baseline: 1.2223x; 1.2223x over previous
#include <cuda_runtime.h>
#include <cstdint>

typedef unsigned long long ULL;
typedef unsigned char u8;

// ---------------- problem dims ----------------
#define T_  4
#define B_  8
#define S_  1024
#define D_  768
#define HF_ 3072
#define SD_   (S_*D_)
#define SH_   (S_*HF_)
#define BSD_  (B_*SD_)
#define BSH_  (B_*SH_)
#define TBSD_ (T_*BSD_)
#define TBSH_ (T_*BSH_)
#define TBD_  (T_*B_*D_)
#define BD_   (B_*D_)
#define MROWS_ (T_*B_*S_)

#define KC_  256   // Eigen gebp k-panel (confirmed R4)

// bn-stat stages
#define ST_Q   0
#define ST_V   1
#define ST_K   2
#define ST_ATT 3
#define ST_O1  4
#define ST_O2  5

// ---------------- device scratch ----------------
__device__ u8    g_sp  [TBSD_];
__device__ float g_q   [TBSD_];
__device__ float g_k   [TBSD_];
__device__ float g_v   [TBSD_];
__device__ u8    g_qs  [TBSD_];
__device__ u8    g_ks  [TBSD_];
__device__ u8    g_vs  [TBSD_];
__device__ u8    g_qkvm[TBSD_];
__device__ float g_att [TBSD_];
__device__ float g_h   [TBSD_];
__device__ u8    g_sp2 [TBSD_];
__device__ float g_o1  [TBSH_];
__device__ u8    g_s1  [TBSH_];
__device__ float g_o2  [TBSD_];
__device__ int   g_qkp [4*TBD_];
__device__ u8    g_qks [TBD_];
__device__ float g_part[8*512];
__device__ float g_gsum[6][256*32];   // per-GEMM-block sums (pass-A fused)
__device__ float g_mean [6*8];
__device__ float g_denom[6*8];

// pointer tables (capture-safe: host never queries symbols)
__device__ u8*    g_ptrB[4];
__device__ float* g_ptrF[6];
__global__ void k_init_ptrs() {
    if (threadIdx.x == 0 && blockIdx.x == 0) {
        g_ptrB[0] = g_sp;  g_ptrB[1] = g_qkvm; g_ptrB[2] = g_sp2; g_ptrB[3] = g_s1;
        g_ptrF[0] = g_q;   g_ptrF[1] = g_k;    g_ptrF[2] = g_v;
        g_ptrF[3] = g_att; g_ptrF[4] = g_o1;   g_ptrF[5] = g_o2;
    }
}

// ---------------- f32x2 helpers (bitwise 2x IEEE fp32 ops) ----------------
__device__ __forceinline__ ULL pack2(float v) {
    ULL r; asm("mov.b64 %0, {%1, %1};" : "=l"(r) : "f"(v)); return r;
}
__device__ __forceinline__ void fma2(ULL& d, ULL a, ULL b) {
    asm("fma.rn.f32x2 %0, %1, %2, %0;" : "+l"(d) : "l"(a), "l"(b));
}
__device__ __forceinline__ ULL add2(ULL a, ULL b) {
    ULL r; asm("add.rn.f32x2 %0, %1, %2;" : "=l"(r) : "l"(a), "l"(b)); return r;
}
__device__ __forceinline__ float2 unpack2(ULL v) {
    float2 r; asm("mov.b64 {%0, %1}, %2;" : "=f"(r.x), "=f"(r.y) : "l"(v)); return r;
}

// ---------------- SGEMM v4 ----------------
// C[M,N] = A[M,K] @ B[K,N] (+bias), A = binary spikes (uint8).
// 128x128 tile, BK=8, 256 threads, 8x8 microtile.
// Inner loop IDENTICAL to R4 (proven): float As/Bs, pack2 in regs, serial
// ascending-k FFMA2 chain in part, FADD flush to acc every KC_=256 k's,
// bias added once at the end.  Double-buffered smem, ONE sync per tile.
// Epilogue additionally reduces the block's C-sum (fused BN pass A).
__global__ __launch_bounds__(256, 2)
void sgemm4(int aSel, const float* __restrict__ Bm, const float* __restrict__ bias,
            int cSel, int N, int K)
{
    __shared__ __align__(16) float As[2][8][128];
    __shared__ __align__(16) float Bs[2][8][128];
    __shared__ float rs[256];

    const u8* __restrict__ A = g_ptrB[aSel];
    float* __restrict__ C = g_ptrF[cSel];

    const int tid = threadIdx.x;
    const int bn = blockIdx.x, bm = blockIdx.y;
    const int tx = tid & 15, ty = tid >> 4;
    const int arow = tid >> 1, acol = (tid & 1) * 4;
    const int brow = tid >> 5, bcol = (tid & 31) * 4;

    const u8*    Ag = A  + (size_t)(bm * 128 + arow) * K + acol;
    const float* Bg = Bm + (size_t)brow * N + bn * 128 + bcol;

    ULL acc[8][4], part[8][4];
#pragma unroll
    for (int i = 0; i < 8; i++)
#pragma unroll
        for (int j = 0; j < 4; j++) { acc[i][j] = 0ULL; part[i][j] = 0ULL; }

    // prefetch + store tile 0
    uchar4 av = *(const uchar4*)(Ag);
    float4 bv = *(const float4*)(Bg);
    As[0][acol + 0][arow] = (float)av.x;
    As[0][acol + 1][arow] = (float)av.y;
    As[0][acol + 2][arow] = (float)av.z;
    As[0][acol + 3][arow] = (float)av.w;
    *(float4*)&Bs[0][brow][bcol] = bv;
    __syncthreads();

    int buf = 0;
    for (int k0 = 0; k0 < K; k0 += 8) {
        const bool more = (k0 + 8) < K;
        if (more) {
            av = *(const uchar4*)(Ag + k0 + 8);
            bv = *(const float4*)(Bg + (size_t)(k0 + 8) * N);
        }

#pragma unroll
        for (int kk = 0; kk < 8; kk++) {
            float a[8];
            *(float4*)(a)     = *(const float4*)&As[buf][kk][ty * 8];
            *(float4*)(a + 4) = *(const float4*)&As[buf][kk][ty * 8 + 4];
            ULL b2[4];
            const ULL* bp = (const ULL*)&Bs[buf][kk][tx * 8];
            b2[0] = bp[0]; b2[1] = bp[1]; b2[2] = bp[2]; b2[3] = bp[3];
#pragma unroll
            for (int i = 0; i < 8; i++) {
                ULL a2 = pack2(a[i]);
#pragma unroll
                for (int j = 0; j < 4; j++) fma2(part[i][j], a2, b2[j]);
            }
        }

        if (more) {
            int nb = buf ^ 1;
            As[nb][acol + 0][arow] = (float)av.x;
            As[nb][acol + 1][arow] = (float)av.y;
            As[nb][acol + 2][arow] = (float)av.z;
            As[nb][acol + 3][arow] = (float)av.w;
            *(float4*)&Bs[nb][brow][bcol] = bv;
            __syncthreads();
        }

        // Eigen panel boundary: FADD-flush serial chain into outer accumulator
        if (((k0 + 8) & (KC_ - 1)) == 0) {
#pragma unroll
            for (int i = 0; i < 8; i++)
#pragma unroll
                for (int j = 0; j < 4; j++) {
                    acc[i][j] = add2(acc[i][j], part[i][j]);
                    part[i][j] = 0ULL;
                }
        }
        buf ^= 1;
    }

    float bb[8];
#pragma unroll
    for (int j = 0; j < 8; j++)
        bb[j] = bias ? bias[bn * 128 + tx * 8 + j] : 0.0f;

    float tsum = 0.0f;
#pragma unroll
    for (int i = 0; i < 8; i++) {
        float* Cp = C + (size_t)(bm * 128 + ty * 8 + i) * N + bn * 128 + tx * 8;
        float2 p0 = unpack2(acc[i][0]), p1 = unpack2(acc[i][1]);
        float2 p2 = unpack2(acc[i][2]), p3 = unpack2(acc[i][3]);
        float4 r0 = make_float4(p0.x + bb[0], p0.y + bb[1], p1.x + bb[2], p1.y + bb[3]);
        float4 r1 = make_float4(p2.x + bb[4], p2.y + bb[5], p3.x + bb[6], p3.y + bb[7]);
        *(float4*)Cp       = r0;
        *(float4*)(Cp + 4) = r1;
        tsum += r0.x + r0.y + r0.z + r0.w + r1.x + r1.y + r1.z + r1.w;
    }

    // fused BN pass A: deterministic block-level sum
    rs[tid] = tsum;
    __syncthreads();
    for (int o = 128; o > 0; o >>= 1) {
        if (tid < o) rs[tid] += rs[tid + o];
        __syncthreads();
    }
    if (tid == 0) g_gsum[cSel][bm * 32 + bn] = rs[0];
}

// finalize mean from fused block sums (fixed order, double combine)
// For batch b, contributing bm = t*64 + b*8 + j  (t<4, j<8), bn < nbn.
__global__ void k_finA2(int stage, int cSel, int nbn, float E) {
    int b = blockIdx.x, tid = threadIdx.x;
    int total = 32 * nbn;
    double s = 0.0;
    for (int i = tid; i < total; i += 256) {
        int g = i / nbn, bnn = i - g * nbn;
        int t = g >> 3, j = g & 7;
        int bm = t * 64 + b * 8 + j;
        s += (double)g_gsum[cSel][bm * 32 + bnn];
    }
    __shared__ double sh[256];
    sh[tid] = s; __syncthreads();
    for (int o = 128; o > 0; o >>= 1) { if (tid < o) sh[tid] += sh[tid + o]; __syncthreads(); }
    if (tid == 0) g_mean[stage * 8 + b] = __fdiv_rn((float)sh[0], E);
}

// ---------------- IF on input x -> sp bytes ----------------
__global__ void k_ifx(const float* __restrict__ x) {
    int j = blockIdx.x * blockDim.x + threadIdx.x;
    if (j >= BSD_) return;
    float vm = 0.0f;
#pragma unroll
    for (int t = 0; t < T_; t++) {
        int idx = t * BSD_ + j;
        vm += x[idx];
        float s = (vm >= 1.0f) ? 1.0f : 0.0f;
        g_sp[idx] = (u8)s;
        vm *= (1.0f - s);
    }
}

// ---------------- BN pass B: per-batch sum of (x-m)^2 -> denom ----------------
__global__ void k_redB(int sel, int SDv, int stage) {
    const float* __restrict__ X = g_ptrF[sel];
    int b = blockIdx.y;
    float m = g_mean[stage * 8 + b];
    int E = T_ * SDv;
    float s = 0.0f;
    for (int i = blockIdx.x * 256 + threadIdx.x; i < E; i += 512 * 256) {
        int t = i / SDv;
        int r = i - t * SDv;
        float v = X[(size_t)(t * B_ + b) * SDv + r] - m;
        s += v * v;
    }
    __shared__ float sh[256];
    int tid = threadIdx.x;
    sh[tid] = s; __syncthreads();
    for (int o = 128; o > 0; o >>= 1) { if (tid < o) sh[tid] += sh[tid + o]; __syncthreads(); }
    if (tid == 0) g_part[b * 512 + blockIdx.x] = sh[0];
}

__global__ void k_finB(int SDv, int stage) {
    int b = blockIdx.x, tid = threadIdx.x;
    double s = (double)g_part[b * 512 + tid] + (double)g_part[b * 512 + tid + 256];
    __shared__ double sh[256];
    sh[tid] = s; __syncthreads();
    for (int o = 128; o > 0; o >>= 1) { if (tid < o) sh[tid] += sh[tid + o]; __syncthreads(); }
    if (tid == 0) {
        float E = (float)(T_ * SDv);
        float var_f = __fdiv_rn((float)sh[0], E);
        g_denom[stage * 8 + b] = __fsqrt_rn(var_f + 1e-5f);
    }
}

// ---------------- fused BN + IF over Q,V,K with CARRIED membrane ----------------
__global__ void k_ifqvk() {
    int j = blockIdx.x * 256 + threadIdx.x;
    if (j >= BSD_) return;
    int b = j / SD_;
    float mq = g_mean[ST_Q * 8 + b], dq = g_denom[ST_Q * 8 + b];
    float mv = g_mean[ST_V * 8 + b], dv = g_denom[ST_V * 8 + b];
    float mk = g_mean[ST_K * 8 + b], dk = g_denom[ST_K * 8 + b];
    float vm = 0.0f;
#pragma unroll
    for (int t = 0; t < T_; t++) {
        int idx = t * BSD_ + j;
        vm += __fdiv_rn(g_q[idx] - mq, dq);
        float s = (vm >= 1.0f) ? 1.0f : 0.0f;
        g_qs[idx] = (u8)s;
        vm *= (1.0f - s);
    }
#pragma unroll
    for (int t = 0; t < T_; t++) {
        int idx = t * BSD_ + j;
        vm += __fdiv_rn(g_v[idx] - mv, dv);
        float s = (vm >= 1.0f) ? 1.0f : 0.0f;
        g_vs[idx] = (u8)s;
        vm *= (1.0f - s);
    }
#pragma unroll
    for (int t = 0; t < T_; t++) {
        int idx = t * BSD_ + j;
        vm += __fdiv_rn(g_k[idx] - mk, dk);
        float s = (vm >= 1.0f) ? 1.0f : 0.0f;
        g_ks[idx] = (u8)s;
        vm *= (1.0f - s);
    }
}

// ---------------- QK: integer seq-reduction (exact) ----------------
__global__ void k_qk() {
    int d = blockIdx.x * 256 + threadIdx.x;
    int tb = blockIdx.y;
    int sp = blockIdx.z;
    int acc = 0;
    int s0 = sp * 256;
    for (int s = s0; s < s0 + 256; s++) {
        size_t idx = ((size_t)tb * S_ + s) * D_ + d;
        acc += (int)(g_qs[idx] & g_ks[idx]);
    }
    g_qkp[sp * TBD_ + tb * D_ + d] = acc;
}

// QKs = IF(QK) over t (integers exact in fp32)
__global__ void k_qks() {
    int i = blockIdx.x * 256 + threadIdx.x;
    if (i >= BD_) return;
    int b = i / D_, d = i - b * D_;
    float vm = 0.0f;
#pragma unroll
    for (int t = 0; t < T_; t++) {
        int idx = (t * B_ + b) * D_ + d;
        int qk = g_qkp[idx] + g_qkp[TBD_ + idx] + g_qkp[2 * TBD_ + idx] +
                 g_qkp[3 * TBD_ + idx];
        vm += (float)qk;
        float s = (vm >= 1.0f) ? 1.0f : 0.0f;
        g_qks[idx] = (u8)s;
        vm *= (1.0f - s);
    }
}

// QKV spikes = Vs & QKs
__global__ void k_qkvm() {
    int idx = blockIdx.x * 256 + threadIdx.x;
    if (idx >= TBSD_) return;
    int d = idx % D_;
    int tb = idx / SD_;
    g_qkvm[idx] = g_vs[idx] & g_qks[tb * D_ + d];
}

// h = sp + bn(att); sp2 = IF(h)
__global__ void k_hsp2() {
    int j = blockIdx.x * 256 + threadIdx.x;
    if (j >= BSD_) return;
    int b = j / SD_;
    float m = g_mean[ST_ATT * 8 + b], dn = g_denom[ST_ATT * 8 + b];
    float vm = 0.0f;
#pragma unroll
    for (int t = 0; t < T_; t++) {
        int idx = t * BSD_ + j;
        float hval = (float)g_sp[idx] + __fdiv_rn(g_att[idx] - m, dn);
        g_h[idx] = hval;
        vm += hval;
        float s = (vm >= 1.0f) ? 1.0f : 0.0f;
        g_sp2[idx] = (u8)s;
        vm *= (1.0f - s);
    }
}

// s1 = IF(bn(o1))
__global__ void k_s1() {
    int j = blockIdx.x * 256 + threadIdx.x;
    if (j >= BSH_) return;
    int b = j / SH_;
    float m = g_mean[ST_O1 * 8 + b], dn = g_denom[ST_O1 * 8 + b];
    float vm = 0.0f;
#pragma unroll
    for (int t = 0; t < T_; t++) {
        int idx = t * BSH_ + j;
        vm += __fdiv_rn(g_o1[idx] - m, dn);
        float s = (vm >= 1.0f) ? 1.0f : 0.0f;
        g_s1[idx] = (u8)s;
        vm *= (1.0f - s);
    }
}

// out = h + bn(o2)
__global__ void k_out(float* __restrict__ out) {
    int idx = blockIdx.x * 256 + threadIdx.x;
    if (idx >= TBSD_) return;
    int b = (idx / SD_) % B_;
    float m = g_mean[ST_O2 * 8 + b], dn = g_denom[ST_O2 * 8 + b];
    out[idx] = g_h[idx] + __fdiv_rn(g_o2[idx] - m, dn);
}

// ---------------- launch (kernel launches ONLY — capture-safe) ----------------
extern "C" void kernel_launch(void* const* d_in, const int* in_sizes, int n_in,
                              void* d_out, int out_size) {
    (void)in_sizes; (void)n_in; (void)out_size;
    const float* x  = (const float*)d_in[0];
    const float* wq = (const float*)d_in[1];
    const float* wk = (const float*)d_in[2];
    const float* wv = (const float*)d_in[3];
    const float* wo = (const float*)d_in[4];
    const float* w1 = (const float*)d_in[5];
    const float* b1 = (const float*)d_in[6];
    const float* w2 = (const float*)d_in[7];
    const float* b2 = (const float*)d_in[8];
    float* out = (float*)d_out;

    const int EW = 256;
    const float E_SD = (float)(T_ * SD_);
    const float E_SH = (float)(T_ * SH_);
    k_init_ptrs<<<1, 32>>>();

    // 1) sp = IF(x)
    k_ifx<<<BSD_ / EW, EW>>>(x);

    // 2) Q,K,V GEMMs (A = sp bytes), pass-A sums fused in epilogue
    sgemm4<<<dim3(6, 256), 256>>>(0, wq, nullptr, 0, D_, D_);
    sgemm4<<<dim3(6, 256), 256>>>(0, wk, nullptr, 1, D_, D_);
    sgemm4<<<dim3(6, 256), 256>>>(0, wv, nullptr, 2, D_, D_);

    // 3) BN stats: mean from fused sums, variance two-pass
    k_finA2<<<8, 256>>>(ST_Q, 0, 6, E_SD);
    k_finA2<<<8, 256>>>(ST_V, 2, 6, E_SD);
    k_finA2<<<8, 256>>>(ST_K, 1, 6, E_SD);
    k_redB<<<dim3(512, 8), 256>>>(0, SD_, ST_Q); k_finB<<<8, 256>>>(SD_, ST_Q);
    k_redB<<<dim3(512, 8), 256>>>(2, SD_, ST_V); k_finB<<<8, 256>>>(SD_, ST_V);
    k_redB<<<dim3(512, 8), 256>>>(1, SD_, ST_K); k_finB<<<8, 256>>>(SD_, ST_K);

    // 4) fused BN+IF, membrane carried Q -> V -> K
    k_ifqvk<<<BSD_ / EW, EW>>>();

    // 5) QK (integer) + IF + QKV spikes
    k_qk<<<dim3(D_ / 256, T_ * B_, 4), 256>>>();
    k_qks<<<BD_ / EW, EW>>>();
    k_qkvm<<<TBSD_ / EW, EW>>>();

    // 6) att = QKV @ wo + BN stats
    sgemm4<<<dim3(6, 256), 256>>>(1, wo, nullptr, 3, D_, D_);
    k_finA2<<<8, 256>>>(ST_ATT, 3, 6, E_SD);
    k_redB<<<dim3(512, 8), 256>>>(3, SD_, ST_ATT); k_finB<<<8, 256>>>(SD_, ST_ATT);

    // 7) h = sp + bn(att); sp2 = IF(h)
    k_hsp2<<<BSD_ / EW, EW>>>();

    // 8) o1 = sp2 @ w1 + b1; BN; s1 = IF(bn(o1))
    sgemm4<<<dim3(24, 256), 256>>>(2, w1, b1, 4, HF_, D_);
    k_finA2<<<8, 256>>>(ST_O1, 4, 24, E_SH);
    k_redB<<<dim3(512, 8), 256>>>(4, SH_, ST_O1); k_finB<<<8, 256>>>(SH_, ST_O1);
    k_s1<<<BSH_ / EW, EW>>>();

    // 9) o2 = s1 @ w2 + b2; BN
    sgemm4<<<dim3(6, 256), 256>>>(3, w2, b2, 5, D_, HF_);
    k_finA2<<<8, 256>>>(ST_O2, 5, 6, E_SD);
    k_redB<<<dim3(512, 8), 256>>>(5, SD_, ST_O2); k_finB<<<8, 256>>>(SD_, ST_O2);

    // 10) out = h + bn(o2)
    k_out<<<TBSD_ / EW, EW>>>(out);
}

// round 8
// speedup vs baseline: 1.4308x; 1.1706x over previous
#include <cuda_runtime.h>
#include <cstdint>

typedef unsigned long long ULL;
typedef unsigned char u8;

// ---------------- problem dims ----------------
#define T_  4
#define B_  8
#define S_  1024
#define D_  768
#define HF_ 3072
#define SD_   (S_*D_)
#define SH_   (S_*HF_)
#define BSD_  (B_*SD_)
#define BSH_  (B_*SH_)
#define TBSD_ (T_*BSD_)
#define TBSH_ (T_*BSH_)
#define TBD_  (T_*B_*D_)
#define BD_   (B_*D_)
#define MROWS_ (T_*B_*S_)

#define KC_  256   // Eigen gebp k-panel (confirmed R4)

// bn-stat stages
#define ST_Q   0
#define ST_V   1
#define ST_K   2
#define ST_ATT 3
#define ST_O1  4
#define ST_O2  5

// ---------------- device scratch ----------------
__device__ u8    g_sp  [TBSD_];
__device__ float g_q   [TBSD_];
__device__ float g_k   [TBSD_];
__device__ float g_v   [TBSD_];
__device__ u8    g_qs  [TBSD_];
__device__ u8    g_ks  [TBSD_];
__device__ u8    g_vs  [TBSD_];
__device__ u8    g_qkvm[TBSD_];
__device__ float g_att [TBSD_];
__device__ float g_h   [TBSD_];
__device__ u8    g_sp2 [TBSD_];
__device__ float g_o1  [TBSH_];
__device__ u8    g_s1  [TBSH_];
__device__ float g_o2  [TBSD_];
__device__ int   g_qkp [4*TBD_];
__device__ u8    g_qks [TBD_];
__device__ float g_part[8*512];
__device__ float g_mean [6*8];
__device__ float g_denom[6*8];

// f32 TRANSPOSED (k-major) spike matrices for GEMM A operands (cp.async layout)
__device__ float g_spT  [TBSD_];   // [768][32768]
__device__ float g_qkvmT[TBSD_];
__device__ float g_sp2T [TBSD_];
__device__ float g_s1T  [TBSH_];   // [3072][32768]

// pointer tables (capture-safe: host never queries symbols)
__device__ u8*    g_ptrB[4];
__device__ float* g_ptrT[4];
__device__ float* g_ptrF[6];
__global__ void k_init_ptrs() {
    if (threadIdx.x == 0 && blockIdx.x == 0) {
        g_ptrB[0] = g_sp;  g_ptrB[1] = g_qkvm; g_ptrB[2] = g_sp2; g_ptrB[3] = g_s1;
        g_ptrT[0] = g_spT; g_ptrT[1] = g_qkvmT; g_ptrT[2] = g_sp2T; g_ptrT[3] = g_s1T;
        g_ptrF[0] = g_q;   g_ptrF[1] = g_k;    g_ptrF[2] = g_v;
        g_ptrF[3] = g_att; g_ptrF[4] = g_o1;   g_ptrF[5] = g_o2;
    }
}

// ---------------- f32x2 helpers (bitwise 2x IEEE fp32 ops) ----------------
__device__ __forceinline__ ULL pack2(float v) {
    ULL r; asm("mov.b64 %0, {%1, %1};" : "=l"(r) : "f"(v)); return r;
}
__device__ __forceinline__ void fma2(ULL& d, ULL a, ULL b) {
    asm("fma.rn.f32x2 %0, %1, %2, %0;" : "+l"(d) : "l"(a), "l"(b));
}
__device__ __forceinline__ ULL add2(ULL a, ULL b) {
    ULL r; asm("add.rn.f32x2 %0, %1, %2;" : "=l"(r) : "l"(a), "l"(b)); return r;
}
__device__ __forceinline__ float2 unpack2(ULL v) {
    float2 r; asm("mov.b64 {%0, %1}, %2;" : "=f"(r.x), "=f"(r.y) : "l"(v)); return r;
}

// ---------------- cp.async helpers ----------------
__device__ __forceinline__ void cp_async16(uint32_t smem, const void* g) {
    asm volatile("cp.async.cg.shared.global [%0], [%1], 16;" :: "r"(smem), "l"(g));
}
__device__ __forceinline__ void cp_commit() {
    asm volatile("cp.async.commit_group;");
}
__device__ __forceinline__ void cp_wait2() {
    asm volatile("cp.async.wait_group 2;");
}

// ---------------- SGEMM v5: 4-stage cp.async pipeline ----------------
// C[M,N] = A_T^T[M,K] @ B[K,N] (+bias); A_T is f32 [K][M] (k-major spikes).
// 128x128 tile, BK=8, 256 threads, 8x8 microtile.
// Inner arithmetic BITWISE identical to R4: serial ascending-k FFMA2 chain in
// part, FADD flush into acc every KC_=256 k's, bias once at the end.
__global__ __launch_bounds__(256, 2)
void sgemm5(int aSel, const float* __restrict__ Bm, const float* __restrict__ bias,
            int cSel, int N, int K)
{
    __shared__ __align__(16) float As[4][8][128];
    __shared__ __align__(16) float Bs[4][8][128];

    const float* __restrict__ A = g_ptrT[aSel];
    float* __restrict__ C = g_ptrF[cSel];

    const int tid = threadIdx.x;
    const int bn = blockIdx.x, bm = blockIdx.y;
    const int tx = tid & 15, ty = tid >> 4;
    const int lrow = tid >> 5;           // 0..7 (k within tile)
    const int lcol = (tid & 31) * 4;     // 0..124

    const float* Ag = A + (size_t)lrow * MROWS_ + bm * 128 + lcol;
    const float* Bg = Bm + (size_t)lrow * N + bn * 128 + lcol;

    uint32_t sA[4], sB[4];
#pragma unroll
    for (int s = 0; s < 4; s++) {
        sA[s] = (uint32_t)__cvta_generic_to_shared(&As[s][lrow][lcol]);
        sB[s] = (uint32_t)__cvta_generic_to_shared(&Bs[s][lrow][lcol]);
    }

    const int T = K / 8;

    // prologue: issue 3 stages
#pragma unroll
    for (int t = 0; t < 3; t++) {
        cp_async16(sA[t], Ag + (size_t)t * 8 * MROWS_);
        cp_async16(sB[t], Bg + (size_t)t * 8 * N);
        cp_commit();
    }
    const float* Agt = Ag + (size_t)24 * MROWS_;
    const float* Bgt = Bg + (size_t)24 * N;

    ULL acc[8][4], part[8][4];
#pragma unroll
    for (int i = 0; i < 8; i++)
#pragma unroll
        for (int j = 0; j < 4; j++) { acc[i][j] = 0ULL; part[i][j] = 0ULL; }

    for (int t = 0; t < T; t++) {
        cp_wait2();
        __syncthreads();

        if (t + 3 < T) {
            int st = (t + 3) & 3;
            cp_async16(sA[st], Agt);
            cp_async16(sB[st], Bgt);
            Agt += (size_t)8 * MROWS_;
            Bgt += (size_t)8 * N;
        }
        cp_commit();

        const int buf = t & 3;
#pragma unroll
        for (int kk = 0; kk < 8; kk++) {
            float a[8];
            *(float4*)(a)     = *(const float4*)&As[buf][kk][ty * 8];
            *(float4*)(a + 4) = *(const float4*)&As[buf][kk][ty * 8 + 4];
            ULL b2[4];
            const ULL* bp = (const ULL*)&Bs[buf][kk][tx * 8];
            b2[0] = bp[0]; b2[1] = bp[1]; b2[2] = bp[2]; b2[3] = bp[3];
#pragma unroll
            for (int i = 0; i < 8; i++) {
                ULL a2 = pack2(a[i]);
#pragma unroll
                for (int j = 0; j < 4; j++) fma2(part[i][j], a2, b2[j]);
            }
        }

        // Eigen panel boundary: FADD-flush serial chain into outer accumulator
        if (((t + 1) & 31) == 0) {
#pragma unroll
            for (int i = 0; i < 8; i++)
#pragma unroll
                for (int j = 0; j < 4; j++) {
                    acc[i][j] = add2(acc[i][j], part[i][j]);
                    part[i][j] = 0ULL;
                }
        }
    }

    float bb[8];
#pragma unroll
    for (int j = 0; j < 8; j++)
        bb[j] = bias ? bias[bn * 128 + tx * 8 + j] : 0.0f;

#pragma unroll
    for (int i = 0; i < 8; i++) {
        float* Cp = C + (size_t)(bm * 128 + ty * 8 + i) * N + bn * 128 + tx * 8;
        float2 p0 = unpack2(acc[i][0]), p1 = unpack2(acc[i][1]);
        float2 p2 = unpack2(acc[i][2]), p3 = unpack2(acc[i][3]);
        *(float4*)Cp       = make_float4(p0.x + bb[0], p0.y + bb[1], p1.x + bb[2], p1.y + bb[3]);
        *(float4*)(Cp + 4) = make_float4(p2.x + bb[4], p2.y + bb[5], p3.x + bb[6], p3.y + bb[7]);
    }
}

// ---------------- u8 [M][K] -> f32 [K][M] transpose (coalesced both sides) ----------------
__global__ void k_tr(int sel, int K) {
    __shared__ float tile[32][33];
    const u8* __restrict__ X = g_ptrB[sel];
    float* __restrict__ Y = g_ptrT[sel];
    int kb = blockIdx.x * 32, mb = blockIdx.y * 32;
    int tx = threadIdx.x & 31, tg = threadIdx.x >> 5;
#pragma unroll
    for (int i = 0; i < 4; i++) {
        int r = tg + i * 8;   // m_local
        tile[tx][r] = (float)X[(size_t)(mb + r) * K + kb + tx];
    }
    __syncthreads();
#pragma unroll
    for (int i = 0; i < 4; i++) {
        int r = tg + i * 8;   // k_local
        Y[(size_t)(kb + r) * MROWS_ + mb + tx] = tile[r][tx];
    }
}

// ---------------- IF on input x -> sp bytes ----------------
__global__ void k_ifx(const float* __restrict__ x) {
    int j = blockIdx.x * blockDim.x + threadIdx.x;
    if (j >= BSD_) return;
    float vm = 0.0f;
#pragma unroll
    for (int t = 0; t < T_; t++) {
        int idx = t * BSD_ + j;
        vm += x[idx];
        float s = (vm >= 1.0f) ? 1.0f : 0.0f;
        g_sp[idx] = (u8)s;
        vm *= (1.0f - s);
    }
}

// ---------------- BN pass A: per-batch sum -> mean ----------------
__global__ void k_redA(int sel, int SDv) {
    const float* __restrict__ X = g_ptrF[sel];
    int b = blockIdx.y;
    int E = T_ * SDv;
    float s = 0.0f;
    for (int i = blockIdx.x * 256 + threadIdx.x; i < E; i += 512 * 256) {
        int t = i / SDv;
        int r = i - t * SDv;
        s += X[(size_t)(t * B_ + b) * SDv + r];
    }
    __shared__ float sh[256];
    int tid = threadIdx.x;
    sh[tid] = s; __syncthreads();
    for (int o = 128; o > 0; o >>= 1) { if (tid < o) sh[tid] += sh[tid + o]; __syncthreads(); }
    if (tid == 0) g_part[b * 512 + blockIdx.x] = sh[0];
}

__global__ void k_finA(int SDv, int stage) {
    int b = blockIdx.x, tid = threadIdx.x;
    double s = (double)g_part[b * 512 + tid] + (double)g_part[b * 512 + tid + 256];
    __shared__ double sh[256];
    sh[tid] = s; __syncthreads();
    for (int o = 128; o > 0; o >>= 1) { if (tid < o) sh[tid] += sh[tid + o]; __syncthreads(); }
    if (tid == 0) {
        float E = (float)(T_ * SDv);
        g_mean[stage * 8 + b] = __fdiv_rn((float)sh[0], E);
    }
}

// ---------------- BN pass B: per-batch sum of (x-m)^2 -> denom ----------------
__global__ void k_redB(int sel, int SDv, int stage) {
    const float* __restrict__ X = g_ptrF[sel];
    int b = blockIdx.y;
    float m = g_mean[stage * 8 + b];
    int E = T_ * SDv;
    float s = 0.0f;
    for (int i = blockIdx.x * 256 + threadIdx.x; i < E; i += 512 * 256) {
        int t = i / SDv;
        int r = i - t * SDv;
        float v = X[(size_t)(t * B_ + b) * SDv + r] - m;
        s += v * v;
    }
    __shared__ float sh[256];
    int tid = threadIdx.x;
    sh[tid] = s; __syncthreads();
    for (int o = 128; o > 0; o >>= 1) { if (tid < o) sh[tid] += sh[tid + o]; __syncthreads(); }
    if (tid == 0) g_part[b * 512 + blockIdx.x] = sh[0];
}

__global__ void k_finB(int SDv, int stage) {
    int b = blockIdx.x, tid = threadIdx.x;
    double s = (double)g_part[b * 512 + tid] + (double)g_part[b * 512 + tid + 256];
    __shared__ double sh[256];
    sh[tid] = s; __syncthreads();
    for (int o = 128; o > 0; o >>= 1) { if (tid < o) sh[tid] += sh[tid + o]; __syncthreads(); }
    if (tid == 0) {
        float E = (float)(T_ * SDv);
        float var_f = __fdiv_rn((float)sh[0], E);
        g_denom[stage * 8 + b] = __fsqrt_rn(var_f + 1e-5f);
    }
}

// ---------------- fused BN + IF over Q,V,K with CARRIED membrane ----------------
__global__ void k_ifqvk() {
    int j = blockIdx.x * 256 + threadIdx.x;
    if (j >= BSD_) return;
    int b = j / SD_;
    float mq = g_mean[ST_Q * 8 + b], dq = g_denom[ST_Q * 8 + b];
    float mv = g_mean[ST_V * 8 + b], dv = g_denom[ST_V * 8 + b];
    float mk = g_mean[ST_K * 8 + b], dk = g_denom[ST_K * 8 + b];
    float vm = 0.0f;
#pragma unroll
    for (int t = 0; t < T_; t++) {
        int idx = t * BSD_ + j;
        vm += __fdiv_rn(g_q[idx] - mq, dq);
        float s = (vm >= 1.0f) ? 1.0f : 0.0f;
        g_qs[idx] = (u8)s;
        vm *= (1.0f - s);
    }
#pragma unroll
    for (int t = 0; t < T_; t++) {
        int idx = t * BSD_ + j;
        vm += __fdiv_rn(g_v[idx] - mv, dv);
        float s = (vm >= 1.0f) ? 1.0f : 0.0f;
        g_vs[idx] = (u8)s;
        vm *= (1.0f - s);
    }
#pragma unroll
    for (int t = 0; t < T_; t++) {
        int idx = t * BSD_ + j;
        vm += __fdiv_rn(g_k[idx] - mk, dk);
        float s = (vm >= 1.0f) ? 1.0f : 0.0f;
        g_ks[idx] = (u8)s;
        vm *= (1.0f - s);
    }
}

// ---------------- QK: integer seq-reduction (exact) ----------------
__global__ void k_qk() {
    int d = blockIdx.x * 256 + threadIdx.x;
    int tb = blockIdx.y;
    int sp = blockIdx.z;
    int acc = 0;
    int s0 = sp * 256;
    for (int s = s0; s < s0 + 256; s++) {
        size_t idx = ((size_t)tb * S_ + s) * D_ + d;
        acc += (int)(g_qs[idx] & g_ks[idx]);
    }
    g_qkp[sp * TBD_ + tb * D_ + d] = acc;
}

// QKs = IF(QK) over t (integers exact in fp32)
__global__ void k_qks() {
    int i = blockIdx.x * 256 + threadIdx.x;
    if (i >= BD_) return;
    int b = i / D_, d = i - b * D_;
    float vm = 0.0f;
#pragma unroll
    for (int t = 0; t < T_; t++) {
        int idx = (t * B_ + b) * D_ + d;
        int qk = g_qkp[idx] + g_qkp[TBD_ + idx] + g_qkp[2 * TBD_ + idx] +
                 g_qkp[3 * TBD_ + idx];
        vm += (float)qk;
        float s = (vm >= 1.0f) ? 1.0f : 0.0f;
        g_qks[idx] = (u8)s;
        vm *= (1.0f - s);
    }
}

// QKV spikes = Vs & QKs
__global__ void k_qkvm() {
    int idx = blockIdx.x * 256 + threadIdx.x;
    if (idx >= TBSD_) return;
    int d = idx % D_;
    int tb = idx / SD_;
    g_qkvm[idx] = g_vs[idx] & g_qks[tb * D_ + d];
}

// h = sp + bn(att); sp2 = IF(h)
__global__ void k_hsp2() {
    int j = blockIdx.x * 256 + threadIdx.x;
    if (j >= BSD_) return;
    int b = j / SD_;
    float m = g_mean[ST_ATT * 8 + b], dn = g_denom[ST_ATT * 8 + b];
    float vm = 0.0f;
#pragma unroll
    for (int t = 0; t < T_; t++) {
        int idx = t * BSD_ + j;
        float hval = (float)g_sp[idx] + __fdiv_rn(g_att[idx] - m, dn);
        g_h[idx] = hval;
        vm += hval;
        float s = (vm >= 1.0f) ? 1.0f : 0.0f;
        g_sp2[idx] = (u8)s;
        vm *= (1.0f - s);
    }
}

// s1 = IF(bn(o1))
__global__ void k_s1() {
    int j = blockIdx.x * 256 + threadIdx.x;
    if (j >= BSH_) return;
    int b = j / SH_;
    float m = g_mean[ST_O1 * 8 + b], dn = g_denom[ST_O1 * 8 + b];
    float vm = 0.0f;
#pragma unroll
    for (int t = 0; t < T_; t++) {
        int idx = t * BSH_ + j;
        vm += __fdiv_rn(g_o1[idx] - m, dn);
        float s = (vm >= 1.0f) ? 1.0f : 0.0f;
        g_s1[idx] = (u8)s;
        vm *= (1.0f - s);
    }
}

// out = h + bn(o2)
__global__ void k_out(float* __restrict__ out) {
    int idx = blockIdx.x * 256 + threadIdx.x;
    if (idx >= TBSD_) return;
    int b = (idx / SD_) % B_;
    float m = g_mean[ST_O2 * 8 + b], dn = g_denom[ST_O2 * 8 + b];
    out[idx] = g_h[idx] + __fdiv_rn(g_o2[idx] - m, dn);
}

// ---------------- launch (kernel launches ONLY — capture-safe) ----------------
extern "C" void kernel_launch(void* const* d_in, const int* in_sizes, int n_in,
                              void* d_out, int out_size) {
    (void)in_sizes; (void)n_in; (void)out_size;
    const float* x  = (const float*)d_in[0];
    const float* wq = (const float*)d_in[1];
    const float* wk = (const float*)d_in[2];
    const float* wv = (const float*)d_in[3];
    const float* wo = (const float*)d_in[4];
    const float* w1 = (const float*)d_in[5];
    const float* b1 = (const float*)d_in[6];
    const float* w2 = (const float*)d_in[7];
    const float* b2 = (const float*)d_in[8];
    float* out = (float*)d_out;

    const int EW = 256;
    k_init_ptrs<<<1, 32>>>();

    // 1) sp = IF(x), transpose to f32 k-major
    k_ifx<<<BSD_ / EW, EW>>>(x);
    k_tr<<<dim3(D_ / 32, MROWS_ / 32), 256>>>(0, D_);

    // 2) Q,K,V GEMMs
    sgemm5<<<dim3(6, 256), 256>>>(0, wq, nullptr, 0, D_, D_);
    sgemm5<<<dim3(6, 256), 256>>>(0, wk, nullptr, 1, D_, D_);
    sgemm5<<<dim3(6, 256), 256>>>(0, wv, nullptr, 2, D_, D_);

    // 3) BN stats (two-pass) for Q, V, K
    k_redA<<<dim3(512, 8), 256>>>(0, SD_); k_finA<<<8, 256>>>(SD_, ST_Q);
    k_redB<<<dim3(512, 8), 256>>>(0, SD_, ST_Q); k_finB<<<8, 256>>>(SD_, ST_Q);
    k_redA<<<dim3(512, 8), 256>>>(2, SD_); k_finA<<<8, 256>>>(SD_, ST_V);
    k_redB<<<dim3(512, 8), 256>>>(2, SD_, ST_V); k_finB<<<8, 256>>>(SD_, ST_V);
    k_redA<<<dim3(512, 8), 256>>>(1, SD_); k_finA<<<8, 256>>>(SD_, ST_K);
    k_redB<<<dim3(512, 8), 256>>>(1, SD_, ST_K); k_finB<<<8, 256>>>(SD_, ST_K);

    // 4) fused BN+IF, membrane carried Q -> V -> K
    k_ifqvk<<<BSD_ / EW, EW>>>();

    // 5) QK (integer) + IF + QKV spikes, transpose
    k_qk<<<dim3(D_ / 256, T_ * B_, 4), 256>>>();
    k_qks<<<BD_ / EW, EW>>>();
    k_qkvm<<<TBSD_ / EW, EW>>>();
    k_tr<<<dim3(D_ / 32, MROWS_ / 32), 256>>>(1, D_);

    // 6) att = QKV @ wo + BN stats
    sgemm5<<<dim3(6, 256), 256>>>(1, wo, nullptr, 3, D_, D_);
    k_redA<<<dim3(512, 8), 256>>>(3, SD_); k_finA<<<8, 256>>>(SD_, ST_ATT);
    k_redB<<<dim3(512, 8), 256>>>(3, SD_, ST_ATT); k_finB<<<8, 256>>>(SD_, ST_ATT);

    // 7) h = sp + bn(att); sp2 = IF(h), transpose
    k_hsp2<<<BSD_ / EW, EW>>>();
    k_tr<<<dim3(D_ / 32, MROWS_ / 32), 256>>>(2, D_);

    // 8) o1 = sp2 @ w1 + b1; BN; s1 = IF(bn(o1)), transpose
    sgemm5<<<dim3(24, 256), 256>>>(2, w1, b1, 4, HF_, D_);
    k_redA<<<dim3(512, 8), 256>>>(4, SH_); k_finA<<<8, 256>>>(SH_, ST_O1);
    k_redB<<<dim3(512, 8), 256>>>(4, SH_, ST_O1); k_finB<<<8, 256>>>(SH_, ST_O1);
    k_s1<<<BSH_ / EW, EW>>>();
    k_tr<<<dim3(HF_ / 32, MROWS_ / 32), 256>>>(3, HF_);

    // 9) o2 = s1 @ w2 + b2; BN
    sgemm5<<<dim3(6, 256), 256>>>(3, w2, b2, 5, D_, HF_);
    k_redA<<<dim3(512, 8), 256>>>(5, SD_); k_finA<<<8, 256>>>(SD_, ST_O2);
    k_redB<<<dim3(512, 8), 256>>>(5, SD_, ST_O2); k_finB<<<8, 256>>>(SD_, ST_O2);

    // 10) out = h + bn(o2)
    k_out<<<TBSD_ / EW, EW>>>(out);
}